// round 8
// baseline (speedup 1.0000x reference)
#include <cuda_runtime.h>
#include <cuda_bf16.h>
#include <cstdint>

// Problem shapes (fixed by the dataset)
#define Bsz 128
#define Tsz 32
#define Dsz 6400
#define Hsz 1000
#define Asz 4
#define Msz (Bsz * Tsz)   // 4096
#define NPAD 1024

#define EPS 1.5e-3f

// Scratch: h1[m][h] (16.38 MB)
__device__ float g_h1[Msz * Hsz];

// bf16 3-split arrays (hi/mid/lo) for x and W1 (W1 padded to 1024 rows)
__device__ __nv_bfloat16 g_Ah[Msz * Dsz];
__device__ __nv_bfloat16 g_Am[Msz * Dsz];
__device__ __nv_bfloat16 g_Al[Msz * Dsz];
__device__ __nv_bfloat16 g_Bh[NPAD * Dsz];
__device__ __nv_bfloat16 g_Bm[NPAD * Dsz];
__device__ __nv_bfloat16 g_Bl[NPAD * Dsz];

// marginal-neuron lists, per batch element
__device__ int g_cnt[Bsz];
__device__ int g_list[Bsz * Hsz];

__device__ __forceinline__ uint32_t smem_u32(const void* p) {
    uint32_t a;
    asm("{ .reg .u64 t; cvta.to.shared.u64 t, %1; cvt.u32.u64 %0, t; }"
        : "=r"(a) : "l"(p));
    return a;
}
__device__ __forceinline__ unsigned short bf16bits(__nv_bfloat16 h) {
    return *reinterpret_cast<unsigned short*>(&h);
}

// ---------------------------------------------------------------------------
// Prep: 3-way bf16 split of an fp32 matrix (4 elements per thread).
// ---------------------------------------------------------------------------
__global__ __launch_bounds__(256)
void split_kernel(const float* __restrict__ src,
                  __nv_bfloat16* __restrict__ ph,
                  __nv_bfloat16* __restrict__ pm,
                  __nv_bfloat16* __restrict__ pl,
                  long valid, long total)
{
    long i  = (long)blockIdx.x * blockDim.x + threadIdx.x;
    long e0 = i * 4;
    if (e0 >= total) return;
    float4 v = (e0 < valid) ? *(const float4*)(src + e0)
                            : make_float4(0.f, 0.f, 0.f, 0.f);
    float vv[4] = {v.x, v.y, v.z, v.w};
    ushort4 H, M, L;
    unsigned short* Hs = &H.x;
    unsigned short* Ms = &M.x;
    unsigned short* Ls = &L.x;
#pragma unroll
    for (int j = 0; j < 4; j++) {
        __nv_bfloat16 h = __float2bfloat16_rn(vv[j]);
        float r1 = vv[j] - __bfloat162float(h);
        __nv_bfloat16 m = __float2bfloat16_rn(r1);
        float r2 = r1 - __bfloat162float(m);
        __nv_bfloat16 l = __float2bfloat16_rn(r2);
        Hs[j] = bf16bits(h); Ms[j] = bf16bits(m); Ls[j] = bf16bits(l);
    }
    *(ushort4*)(ph + e0) = H;
    *(ushort4*)(pm + e0) = M;
    *(ushort4*)(pl + e0) = L;
}

// ---------------------------------------------------------------------------
// GEMM: h1 = x . W1^T + b1 via warp-level bf16 mma.sync, 6 split products.
// CTA tile 128x128, BK=64 (128B rows, SW128 swizzle), 8 warps (2M x 4N),
// cp.async double-buffered smem (2 x 96KB), fp32 accumulators in registers.
// ---------------------------------------------------------------------------
#define GBK 64
#define KCH (Dsz / GBK)            // 100
#define TILEB 16384                // 128 rows x 128 B
#define STAGEB (6 * TILEB)         // 98304
#define GSMEM (2 * STAGEB)         // 196608

__global__ __launch_bounds__(256)
void gemm_mma_kernel(const float* __restrict__ bias)
{
    extern __shared__ __align__(1024) char sm[];
    const uint32_t sbase = smem_u32(sm);

    const int tid   = threadIdx.x;
    const int lane  = tid & 31;
    const int wid   = tid >> 5;
    const int warpM = wid & 1;
    const int warpN = wid >> 1;
    const int bn    = blockIdx.x;   // 0..7
    const int bm    = blockIdx.y;   // 0..31

    float c[4][4][4];
#pragma unroll
    for (int i = 0; i < 4; i++)
#pragma unroll
        for (int j = 0; j < 4; j++)
#pragma unroll
            for (int k = 0; k < 4; k++) c[i][j][k] = 0.f;

    const __nv_bfloat16* const ap[3] = {g_Ah, g_Am, g_Al};
    const __nv_bfloat16* const bp[3] = {g_Bh, g_Bm, g_Bl};

    int lr[4], lkb[4];
    uint32_t ldsw[4];
#pragma unroll
    for (int u4 = 0; u4 < 4; u4++) {
        int u   = tid + u4 * 256;
        lr[u4]  = u >> 3;
        lkb[u4] = u & 7;
        ldsw[u4] = (uint32_t)(lr[u4] * 128 + ((lkb[u4] ^ (lr[u4] & 7)) << 4));
    }

#define ISSUE_CHUNK(CH, ST)                                                    \
    do {                                                                       \
        const int _kt = (CH) * GBK;                                            \
        const uint32_t _stb = sbase + (ST) * STAGEB;                           \
        _Pragma("unroll")                                                      \
        for (int _u = 0; _u < 4; _u++) {                                       \
            const size_t _offA = (size_t)(bm * 128 + lr[_u]) * Dsz + _kt + lkb[_u] * 8; \
            const size_t _offB = (size_t)(bn * 128 + lr[_u]) * Dsz + _kt + lkb[_u] * 8; \
            _Pragma("unroll")                                                  \
            for (int _t = 0; _t < 3; _t++) {                                   \
                asm volatile("cp.async.cg.shared.global [%0], [%1], 16;"       \
                             :: "r"(_stb + _t * TILEB + ldsw[_u]),             \
                                "l"(ap[_t] + _offA) : "memory");               \
                asm volatile("cp.async.cg.shared.global [%0], [%1], 16;"       \
                             :: "r"(_stb + (3 + _t) * TILEB + ldsw[_u]),       \
                                "l"(bp[_t] + _offB) : "memory");               \
            }                                                                  \
        }                                                                      \
        asm volatile("cp.async.commit_group;" ::: "memory");                   \
    } while (0)

    ISSUE_CHUNK(0, 0);
    ISSUE_CHUNK(1, 1);

    const int pa[6] = {0, 0, 1, 1, 0, 2};
    const int pb[6] = {3, 4, 3, 4, 5, 3};

    for (int ch = 0; ch < KCH; ch++) {
        if (ch < KCH - 1)
            asm volatile("cp.async.wait_group 1;" ::: "memory");
        else
            asm volatile("cp.async.wait_group 0;" ::: "memory");
        __syncthreads();

        const uint32_t stb = sbase + (ch & 1) * STAGEB;

#pragma unroll
        for (int p = 0; p < 6; p++) {
            const uint32_t ab = stb + pa[p] * TILEB;
            const uint32_t bb = stb + pb[p] * TILEB;
#pragma unroll
            for (int ks = 0; ks < 4; ks++) {
                uint32_t a[4][4];
#pragma unroll
                for (int mf = 0; mf < 4; mf++) {
                    const int r  = warpM * 64 + mf * 16 + (lane & 15);
                    const int kb = ks * 2 + (lane >> 4);
                    const uint32_t ad = ab + r * 128 + ((kb ^ (r & 7)) << 4);
                    asm volatile(
                        "ldmatrix.sync.aligned.m8n8.x4.shared.b16 {%0,%1,%2,%3}, [%4];"
                        : "=r"(a[mf][0]), "=r"(a[mf][1]),
                          "=r"(a[mf][2]), "=r"(a[mf][3])
                        : "r"(ad));
                }
                uint32_t b[4][2];
#pragma unroll
                for (int ng = 0; ng < 2; ng++) {
                    const int grp = lane >> 3;
                    const int rr  = warpN * 32 + ng * 16 + (grp >> 1) * 8 + (lane & 7);
                    const int kb  = ks * 2 + (grp & 1);
                    const uint32_t bd = bb + rr * 128 + ((kb ^ (rr & 7)) << 4);
                    asm volatile(
                        "ldmatrix.sync.aligned.m8n8.x4.shared.b16 {%0,%1,%2,%3}, [%4];"
                        : "=r"(b[ng * 2][0]), "=r"(b[ng * 2][1]),
                          "=r"(b[ng * 2 + 1][0]), "=r"(b[ng * 2 + 1][1])
                        : "r"(bd));
                }
#pragma unroll
                for (int mf = 0; mf < 4; mf++)
#pragma unroll
                    for (int nf = 0; nf < 4; nf++)
                        asm volatile(
                            "mma.sync.aligned.m16n8k16.row.col.f32.bf16.bf16.f32 "
                            "{%0,%1,%2,%3}, {%4,%5,%6,%7}, {%8,%9}, {%0,%1,%2,%3};"
                            : "+f"(c[mf][nf][0]), "+f"(c[mf][nf][1]),
                              "+f"(c[mf][nf][2]), "+f"(c[mf][nf][3])
                            : "r"(a[mf][0]), "r"(a[mf][1]),
                              "r"(a[mf][2]), "r"(a[mf][3]),
                              "r"(b[nf][0]), "r"(b[nf][1]));
            }
        }
        __syncthreads();
        if (ch + 2 < KCH) ISSUE_CHUNK(ch + 2, ch & 1);
    }

#pragma unroll
    for (int mf = 0; mf < 4; mf++) {
        const int rg = bm * 128 + warpM * 64 + mf * 16 + (lane >> 2);
#pragma unroll
        for (int nf = 0; nf < 4; nf++) {
            const int cg = bn * 128 + warpN * 32 + nf * 8 + 2 * (lane & 3);
            if (cg < Hsz) {
                const float bv = bias[cg];
                g_h1[(size_t)rg * Hsz + cg]       = c[mf][nf][0] + bv;
                g_h1[(size_t)(rg + 8) * Hsz + cg] = c[mf][nf][2] + bv;
            }
            if (cg + 1 < Hsz) {
                const float bv = bias[cg + 1];
                g_h1[(size_t)rg * Hsz + cg + 1]       = c[mf][nf][1] + bv;
                g_h1[(size_t)(rg + 8) * Hsz + cg + 1] = c[mf][nf][3] + bv;
            }
        }
    }
}

// ---------------------------------------------------------------------------
// Zero the per-batch marginal counters (graph-replay safe).
// ---------------------------------------------------------------------------
__global__ void zero_cnt_kernel() {
    if (threadIdx.x < Bsz) g_cnt[threadIdx.x] = 0;
}

// ---------------------------------------------------------------------------
// Pass 1: layer-1 recurrence on TC h1; flag neurons whose membrane ever
// comes within EPS of threshold (these decisions are not trustworthy).
// Layer-1 updates are elementwise, so this matches any thread mapping.
// ---------------------------------------------------------------------------
__global__ __launch_bounds__(256, 1)
void flag_kernel()
{
    const int b   = blockIdx.x;
    const int tid = threadIdx.x;

    float mem1[4] = {0.f, 0.f, 0.f, 0.f};
    bool  fl[4]   = {false, false, false, false};

    for (int t = 0; t < Tsz; t++) {
        const float* h1row = g_h1 + (size_t)(b * Tsz + t) * Hsz;
#pragma unroll
        for (int j = 0; j < 4; j++) {
            const int h = tid + j * 256;
            if (h < Hsz) {
                const float cur  = h1row[h];
                const float m    = mem1[j];
                const float keep = (m > 1.0f) ? 0.f : 1.f;
                const float mnew = (0.99f * m + cur) * keep;
                mem1[j] = mnew;
                if (fabsf(mnew - 1.0f) < EPS) fl[j] = true;
            }
        }
    }
#pragma unroll
    for (int j = 0; j < 4; j++) {
        const int h = tid + j * 256;
        if (h < Hsz && fl[j]) {
            int idx = atomicAdd(&g_cnt[b], 1);
            g_list[b * Hsz + idx] = h;
        }
    }
}

// ---------------------------------------------------------------------------
// Repair: for each flagged (b,h), recompute h1[b,t,h] for all t with the
// EXACT sequential-k fp32 fmaf chain (k = 0..6399 ascending), matching the
// proven R2 scalar GEMM ordering. One block per b; warp -> flagged entry,
// lane -> timestep. x chunks staged in smem (k-ascending).
// ---------------------------------------------------------------------------
#define CHK 320
#define NCHKS (Dsz / CHK)   // 20

__global__ __launch_bounds__(256, 1)
void repair_kernel(const float* __restrict__ x,    // [128, 32, 6400]
                   const float* __restrict__ W1,   // [1000, 6400]
                   const float* __restrict__ b1)   // [1000]
{
    __shared__ float xs[32][CHK + 1];   // [t][k], pad -> conflict-free

    const int b    = blockIdx.x;
    const int cnt  = g_cnt[b];
    if (cnt == 0) return;

    const int tid  = threadIdx.x;
    const int wid  = tid >> 5;
    const int lane = tid & 31;
    const float* xb = x + (size_t)b * Tsz * Dsz;

    for (int r0 = 0; r0 < cnt; r0 += 8) {
        const int  e   = r0 + wid;
        const bool act = (e < cnt);
        const int  h   = act ? g_list[b * Hsz + e] : 0;
        const float* wrow = W1 + (size_t)h * Dsz;
        float acc = 0.f;

        for (int cch = 0; cch < NCHKS; cch++) {
            __syncthreads();
            // stage x[b][0..31][cch*CHK .. +CHK) into smem
            for (int f = tid; f < 32 * (CHK / 4); f += 256) {
                const int t = f / (CHK / 4);
                const int q = f % (CHK / 4);
                float4 v = *(const float4*)(xb + (size_t)t * Dsz + cch * CHK + q * 4);
                xs[t][q * 4 + 0] = v.x;
                xs[t][q * 4 + 1] = v.y;
                xs[t][q * 4 + 2] = v.z;
                xs[t][q * 4 + 3] = v.w;
            }
            __syncthreads();

            if (act) {
                const float* wp = wrow + cch * CHK;
                for (int k = 0; k < CHK; k++)
                    acc = fmaf(xs[lane][k], wp[k], acc);   // strict sequential k
            }
        }
        if (act)
            g_h1[(size_t)(b * Tsz + lane) * Hsz + h] = acc + b1[h];
    }
}

// ---------------------------------------------------------------------------
// Pass 2: full LIF recurrence — VERBATIM the R2-proven 256-thread kernel
// (layer-2 reduction order validated at rel_err 0.0).
// ---------------------------------------------------------------------------
__global__ __launch_bounds__(256, 1)
void snn_recurrence_kernel(const float* __restrict__ W2,   // [4, 1000]
                           const float* __restrict__ b2,   // [4]
                           float* __restrict__ out)        // [128, 32, 4]
{
    __shared__ float sW2[Asz * Hsz];
    __shared__ float red[8][4];

    const int b   = blockIdx.x;
    const int tid = threadIdx.x;

    for (int i = tid; i < Asz * Hsz; i += 256) sW2[i] = W2[i];

    float mem1[4] = {0.f, 0.f, 0.f, 0.f};
    float mem2 = 0.f;
    const float b2v = (tid < Asz) ? b2[tid] : 0.f;

    __syncthreads();

    for (int t = 0; t < Tsz; t++) {
        const float* h1row = g_h1 + (size_t)(b * Tsz + t) * Hsz;
        float acc[4] = {0.f, 0.f, 0.f, 0.f};

#pragma unroll
        for (int j = 0; j < 4; j++) {
            const int h = tid + j * 256;
            if (h < Hsz) {
                const float cur   = h1row[h];
                const float m     = mem1[j];
                const float keep  = (m > 1.0f) ? 0.f : 1.f;
                const float mnew  = (0.99f * m + cur) * keep;
                mem1[j] = mnew;
                if (mnew - 1.0f > 0.f) {
                    acc[0] += sW2[h];
                    acc[1] += sW2[Hsz + h];
                    acc[2] += sW2[2 * Hsz + h];
                    acc[3] += sW2[3 * Hsz + h];
                }
            }
        }

#pragma unroll
        for (int a = 0; a < 4; a++)
#pragma unroll
            for (int off = 16; off > 0; off >>= 1)
                acc[a] += __shfl_down_sync(0xffffffffu, acc[a], off);

        const int warp = tid >> 5;
        if ((tid & 31) == 0) {
            red[warp][0] = acc[0];
            red[warp][1] = acc[1];
            red[warp][2] = acc[2];
            red[warp][3] = acc[3];
        }
        __syncthreads();

        if (tid < Asz) {
            float s = b2v;
#pragma unroll
            for (int w = 0; w < 8; w++) s += red[w][tid];
            const float m    = mem2;
            const float keep = (m > 1.0f) ? 0.f : 1.f;
            const float mnew = (0.99f * m + s) * keep;
            mem2 = mnew;
            out[(size_t)(b * Tsz + t) * Asz + tid] = (mnew - 1.0f > 0.f) ? 1.0f : 0.f;
        }
        __syncthreads();
    }
}

// ---------------------------------------------------------------------------
extern "C" void kernel_launch(void* const* d_in, const int* in_sizes, int n_in,
                              void* d_out, int out_size)
{
    const float* x  = (const float*)d_in[0];   // [128, 32, 6400]
    const float* W1 = (const float*)d_in[1];   // [1000, 6400]
    const float* b1 = (const float*)d_in[2];   // [1000]
    const float* W2 = (const float*)d_in[3];   // [4, 1000]
    const float* b2 = (const float*)d_in[4];   // [4]
    float* out = (float*)d_out;                // [128, 32, 4]

    (void)in_sizes; (void)n_in; (void)out_size;

    cudaFuncSetAttribute(gemm_mma_kernel,
                         cudaFuncAttributeMaxDynamicSharedMemorySize, GSMEM);

    __nv_bfloat16 *ah, *am, *al, *bh, *bm_, *bl;
    cudaGetSymbolAddress((void**)&ah,  g_Ah);
    cudaGetSymbolAddress((void**)&am,  g_Am);
    cudaGetSymbolAddress((void**)&al,  g_Al);
    cudaGetSymbolAddress((void**)&bh,  g_Bh);
    cudaGetSymbolAddress((void**)&bm_, g_Bm);
    cudaGetSymbolAddress((void**)&bl,  g_Bl);

    const long atot = (long)Msz * Dsz;               // 26.2M
    split_kernel<<<(int)(atot / 4 / 256), 256>>>(x, ah, am, al, atot, atot);

    const long btot = (long)NPAD * Dsz;              // 6.55M
    const long bval = (long)Hsz * Dsz;               // 6.40M
    split_kernel<<<(int)(btot / 4 / 256), 256>>>(W1, bh, bm_, bl, bval, btot);

    dim3 ggrid(8, 32);
    gemm_mma_kernel<<<ggrid, 256, GSMEM>>>(b1);

    zero_cnt_kernel<<<1, 128>>>();
    flag_kernel<<<Bsz, 256>>>();
    repair_kernel<<<Bsz, 256>>>(x, W1, b1);

    snn_recurrence_kernel<<<Bsz, 256>>>(W2, b2, out);
}